// round 13
// baseline (speedup 1.0000x reference)
#include <cuda_runtime.h>

#define NN 50000
#define NE 800000
#define L  32
#define NSTEP 10

// ---------------- scratch (device globals; no allocations allowed) ----------
__device__ float g_h[NN * L];     // node latents
__device__ float g_e[NE * L];     // edge latents
__device__ float g_agg[NN * L];   // per-step scatter accumulator
__device__ float g_inv[NN];       // 1/max(indeg,1)
__device__ float g_cnt[NN];       // receiver in-degree

__device__ __forceinline__ float lk(float v) { return v >= 0.f ? v : 0.01f * v; }

// --- packed f32x2 helpers (FFMA2 path; sm_100+) ------------------------------
__device__ __forceinline__ unsigned long long pack2(float x, float y) {
    unsigned long long r;
    asm("mov.b64 %0, {%1, %2};" : "=l"(r) : "f"(x), "f"(y));
    return r;
}
__device__ __forceinline__ void ffma2(unsigned long long& d, unsigned long long a,
                                      unsigned long long b) {
    asm("fma.rn.f32x2 %0, %1, %2, %0;" : "+l"(d) : "l"(a), "l"(b));
}
__device__ __forceinline__ float2 unpack2(unsigned long long v) {
    float2 r;
    asm("mov.b64 {%0, %1}, %2;" : "=f"(r.x), "=f"(r.y) : "l"(v));
    return r;
}
__device__ __forceinline__ void red_v4(float* p, float4 o) {
    asm volatile("red.global.add.v4.f32 [%0], {%1, %2, %3, %4};"
                 :: "l"(p), "f"(o.x), "f"(o.y), "f"(o.z), "f"(o.w) : "memory");
}

// ---------------- tiny utility kernels --------------------------------------
__global__ void zero_cnt_agg_k() {
    int i = blockIdx.x * blockDim.x + threadIdx.x;
    if (i < NN) g_cnt[i] = 0.f;
    if (i < NN * L) g_agg[i] = 0.f;   // launched with NN*L coverage
}

__global__ void inv_k() {
    int i = blockIdx.x * blockDim.x + threadIdx.x;
    if (i < NN) g_inv[i] = 1.f / fmaxf(g_cnt[i], 1.f);
}

// ---------------- encoders --------------------------------------------------
__global__ __launch_bounds__(256) void node_enc_k(
    const float* __restrict__ x, const float* __restrict__ W,
    const float* __restrict__ b) {
    __shared__ float Ws[6 * L];
    __shared__ float bs[L];
    int t = threadIdx.x;
    if (t < 6 * L) Ws[t] = W[t];
    if (t < L) bs[t] = b[t];
    __syncthreads();
    int n = blockIdx.x * blockDim.x + t;
    if (n >= NN) return;
    float in[6];
#pragma unroll
    for (int k = 0; k < 6; k++) in[k] = x[n * 6 + k];
#pragma unroll
    for (int j = 0; j < L; j += 4) {
        float4 a = make_float4(bs[j], bs[j + 1], bs[j + 2], bs[j + 3]);
#pragma unroll
        for (int k = 0; k < 6; k++) {
            float4 w = *(const float4*)&Ws[k * L + j];
            a.x = fmaf(in[k], w.x, a.x);
            a.y = fmaf(in[k], w.y, a.y);
            a.z = fmaf(in[k], w.z, a.z);
            a.w = fmaf(in[k], w.w, a.w);
        }
        float4 o = make_float4(lk(a.x), lk(a.y), lk(a.z), lk(a.w));
        *(float4*)&g_h[(size_t)n * L + j] = o;
    }
}

__global__ __launch_bounds__(256) void edge_enc_k(
    const float* __restrict__ ea, const float* __restrict__ W,
    const float* __restrict__ b, const int* __restrict__ rcv) {
    __shared__ float Ws[3 * L];
    __shared__ float bs[L];
    int t = threadIdx.x;
    if (t < 3 * L) Ws[t] = W[t];
    if (t < L) bs[t] = b[t];
    __syncthreads();
    int eid = blockIdx.x * blockDim.x + t;
    if (eid >= NE) return;
    float in[3];
#pragma unroll
    for (int k = 0; k < 3; k++) in[k] = ea[(size_t)eid * 3 + k];
#pragma unroll
    for (int j = 0; j < L; j += 4) {
        float4 a = make_float4(bs[j], bs[j + 1], bs[j + 2], bs[j + 3]);
#pragma unroll
        for (int k = 0; k < 3; k++) {
            float4 w = *(const float4*)&Ws[k * L + j];
            a.x = fmaf(in[k], w.x, a.x);
            a.y = fmaf(in[k], w.y, a.y);
            a.z = fmaf(in[k], w.z, a.z);
            a.w = fmaf(in[k], w.w, a.w);
        }
        float4 o = make_float4(lk(a.x), lk(a.y), lk(a.z), lk(a.w));
        *(float4*)&g_e[(size_t)eid * L + j] = o;
    }
    atomicAdd(&g_cnt[rcv[eid]], 1.f);  // in-degree (reused all steps)
}

// ---------------- per-step edge update (the hot kernel) ----------------------
// m = LN(leaky(concat(e, h[snd], h[rcv]) @ W[96,32] + b)); e += m; agg[rcv] += e
__global__ __launch_bounds__(256) void edge_step_k(
    const float* __restrict__ W, const float* __restrict__ b,
    const float* __restrict__ lns, const float* __restrict__ lnb,
    const int* __restrict__ snd, const int* __restrict__ rcv) {
    __shared__ __align__(16) float Ws[3 * L * L];   // 12 KB
    __shared__ float bs[L], ss[L], os[L];

    // ---- prefetch: indices + own e row, issued BEFORE weight staging so the
    //      LDGs overlap the staging loop + barrier (~hundreds of cycles) ----
    int eid = blockIdx.x * blockDim.x + threadIdx.x;
    bool active = eid < NE;
    int s = 0, r = 0;
    float ein[L];
    float* erow = &g_e[(size_t)(active ? eid : 0) * L];
    if (active) {
        s = snd[eid];
        r = rcv[eid];
#pragma unroll
        for (int j = 0; j < L; j += 4) *(float4*)&ein[j] = *(const float4*)&erow[j];
    }

    for (int i = threadIdx.x; i < 3 * L * L; i += 256) Ws[i] = W[i];
    if (threadIdx.x < L) {
        bs[threadIdx.x] = b[threadIdx.x];
        ss[threadIdx.x] = lns[threadIdx.x];
        os[threadIdx.x] = lnb[threadIdx.x];
    }
    __syncthreads();
    if (!active) return;

    // 16 packed accumulators = 32 fp32 lanes
    unsigned long long acc2[L / 2];
#pragma unroll
    for (int j = 0; j < L / 2; j++) acc2[j] = pack2(bs[2 * j], bs[2 * j + 1]);

    // ---- e contribution first (rows 0..L-1); ein already in registers ----
#pragma unroll
    for (int k = 0; k < L; k++) {
        unsigned long long vv = pack2(ein[k], ein[k]);
        const ulonglong2* wrow = (const ulonglong2*)&Ws[k * L];
#pragma unroll
        for (int j2 = 0; j2 < L / 4; j2++) {
            ulonglong2 w = wrow[j2];
            ffma2(acc2[2 * j2], vv, w.x);
            ffma2(acc2[2 * j2 + 1], vv, w.y);
        }
    }

    float in[L];
    // ---- h_src contribution (rows L..2L-1 of W) ----
    {
        const float* row = &g_h[(size_t)s * L];
#pragma unroll
        for (int j = 0; j < L; j += 4) *(float4*)&in[j] = *(const float4*)&row[j];
#pragma unroll
        for (int k = 0; k < L; k++) {
            unsigned long long vv = pack2(in[k], in[k]);
            const ulonglong2* wrow = (const ulonglong2*)&Ws[(L + k) * L];
#pragma unroll
            for (int j2 = 0; j2 < L / 4; j2++) {
                ulonglong2 w = wrow[j2];
                ffma2(acc2[2 * j2], vv, w.x);
                ffma2(acc2[2 * j2 + 1], vv, w.y);
            }
        }
    }
    // ---- h_dst contribution (rows 2L..3L-1) ----
    {
        const float* row = &g_h[(size_t)r * L];
#pragma unroll
        for (int j = 0; j < L; j += 4) *(float4*)&in[j] = *(const float4*)&row[j];
#pragma unroll
        for (int k = 0; k < L; k++) {
            unsigned long long vv = pack2(in[k], in[k]);
            const ulonglong2* wrow = (const ulonglong2*)&Ws[(2 * L + k) * L];
#pragma unroll
            for (int j2 = 0; j2 < L / 4; j2++) {
                ulonglong2 w = wrow[j2];
                ffma2(acc2[2 * j2], vv, w.x);
                ffma2(acc2[2 * j2 + 1], vv, w.y);
            }
        }
    }

    // ---- LeakyReLU + thread-local LayerNorm ----
    float acc[L];
#pragma unroll
    for (int j = 0; j < L / 2; j++) {
        float2 u = unpack2(acc2[j]);
        acc[2 * j] = lk(u.x);
        acc[2 * j + 1] = lk(u.y);
    }
    float mu = 0.f;
#pragma unroll
    for (int j = 0; j < L; j++) mu += acc[j];
    mu *= (1.f / L);
    float var = 0.f;
#pragma unroll
    for (int j = 0; j < L; j++) { float d = acc[j] - mu; var = fmaf(d, d, var); }
    float rs = rsqrtf(var * (1.f / L) + 1e-5f);

    float* arow = &g_agg[(size_t)r * L];
#pragma unroll
    for (int j = 0; j < L; j += 4) {
        float4 o;
        o.x = ein[j]     + fmaf((acc[j]     - mu) * rs, ss[j],     os[j]);
        o.y = ein[j + 1] + fmaf((acc[j + 1] - mu) * rs, ss[j + 1], os[j + 1]);
        o.z = ein[j + 2] + fmaf((acc[j + 2] - mu) * rs, ss[j + 2], os[j + 2]);
        o.w = ein[j + 3] + fmaf((acc[j + 3] - mu) * rs, ss[j + 3], os[j + 3]);
        *(float4*)&erow[j] = o;
        red_v4(&arow[j], o);   // vectorized no-return global reduction
    }
}

// ---------------- per-step node update ---------------------------------------
// u = LN(leaky(concat(h, agg*inv) @ W[64,32] + b)); h += u; then zero agg row
__global__ __launch_bounds__(256) void node_step_k(
    const float* __restrict__ W, const float* __restrict__ b,
    const float* __restrict__ lns, const float* __restrict__ lnb) {
    __shared__ __align__(16) float Ws[2 * L * L];  // 8 KB
    __shared__ float bs[L], ss[L], os[L];

    // prefetch own rows before weight staging
    int n = blockIdx.x * blockDim.x + threadIdx.x;
    bool active = n < NN;
    float inv = 0.f;
    float in[L], hin[L];
    float* arow = &g_agg[(size_t)(active ? n : 0) * L];
    float* hrow = &g_h[(size_t)(active ? n : 0) * L];
    if (active) {
        inv = g_inv[n];
#pragma unroll
        for (int j = 0; j < L; j += 4) {
            *(float4*)&in[j] = *(const float4*)&arow[j];
            *(float4*)&hin[j] = *(const float4*)&hrow[j];
        }
    }

    for (int i = threadIdx.x; i < 2 * L * L; i += 256) Ws[i] = W[i];
    if (threadIdx.x < L) {
        bs[threadIdx.x] = b[threadIdx.x];
        ss[threadIdx.x] = lns[threadIdx.x];
        os[threadIdx.x] = lnb[threadIdx.x];
    }
    __syncthreads();
    if (!active) return;

    // zero the agg row for the next step (after reading)
#pragma unroll
    for (int j = 0; j < L; j += 4)
        *(float4*)&arow[j] = make_float4(0.f, 0.f, 0.f, 0.f);

    unsigned long long acc2[L / 2];
#pragma unroll
    for (int j = 0; j < L / 2; j++) acc2[j] = pack2(bs[2 * j], bs[2 * j + 1]);

    // agg part (rows L..2L-1)
#pragma unroll
    for (int k = 0; k < L; k++) {
        float v = in[k] * inv;
        unsigned long long vv = pack2(v, v);
        const ulonglong2* wrow = (const ulonglong2*)&Ws[(L + k) * L];
#pragma unroll
        for (int j2 = 0; j2 < L / 4; j2++) {
            ulonglong2 w = wrow[j2];
            ffma2(acc2[2 * j2], vv, w.x);
            ffma2(acc2[2 * j2 + 1], vv, w.y);
        }
    }
    // h part (rows 0..L-1)
#pragma unroll
    for (int k = 0; k < L; k++) {
        unsigned long long vv = pack2(hin[k], hin[k]);
        const ulonglong2* wrow = (const ulonglong2*)&Ws[k * L];
#pragma unroll
        for (int j2 = 0; j2 < L / 4; j2++) {
            ulonglong2 w = wrow[j2];
            ffma2(acc2[2 * j2], vv, w.x);
            ffma2(acc2[2 * j2 + 1], vv, w.y);
        }
    }

    float acc[L];
#pragma unroll
    for (int j = 0; j < L / 2; j++) {
        float2 u = unpack2(acc2[j]);
        acc[2 * j] = lk(u.x);
        acc[2 * j + 1] = lk(u.y);
    }
    float mu = 0.f;
#pragma unroll
    for (int j = 0; j < L; j++) mu += acc[j];
    mu *= (1.f / L);
    float var = 0.f;
#pragma unroll
    for (int j = 0; j < L; j++) { float d = acc[j] - mu; var = fmaf(d, d, var); }
    float rs = rsqrtf(var * (1.f / L) + 1e-5f);

#pragma unroll
    for (int j = 0; j < L; j += 4) {
        float4 o;
        o.x = hin[j]     + fmaf((acc[j]     - mu) * rs, ss[j],     os[j]);
        o.y = hin[j + 1] + fmaf((acc[j + 1] - mu) * rs, ss[j + 1], os[j + 1]);
        o.z = hin[j + 2] + fmaf((acc[j + 2] - mu) * rs, ss[j + 2], os[j + 2]);
        o.w = hin[j + 3] + fmaf((acc[j + 3] - mu) * rs, ss[j + 3], os[j + 3]);
        *(float4*)&hrow[j] = o;
    }
}

// ---------------- decoder -----------------------------------------------------
__global__ __launch_bounds__(256) void dec_k(
    const float* __restrict__ W1, const float* __restrict__ b1,
    const float* __restrict__ W2, const float* __restrict__ b2,
    float* __restrict__ out) {
    __shared__ __align__(16) float Ws[L * L];
    __shared__ float b1s[L], w2s[L];
    __shared__ float b2s;
    int t = threadIdx.x;

    int n = blockIdx.x * blockDim.x + t;
    bool active = n < NN;
    float in[L];
    if (active) {
        const float* hrow = &g_h[(size_t)n * L];
#pragma unroll
        for (int j = 0; j < L; j += 4) *(float4*)&in[j] = *(const float4*)&hrow[j];
    }

    for (int i = t; i < L * L; i += 256) Ws[i] = W1[i];
    if (t < L) { b1s[t] = b1[t]; w2s[t] = W2[t]; }
    if (t == 0) b2s = b2[0];
    __syncthreads();
    if (!active) return;

    unsigned long long acc2[L / 2];
#pragma unroll
    for (int j = 0; j < L / 2; j++) acc2[j] = pack2(b1s[2 * j], b1s[2 * j + 1]);
#pragma unroll
    for (int k = 0; k < L; k++) {
        unsigned long long vv = pack2(in[k], in[k]);
        const ulonglong2* wrow = (const ulonglong2*)&Ws[k * L];
#pragma unroll
        for (int j2 = 0; j2 < L / 4; j2++) {
            ulonglong2 w = wrow[j2];
            ffma2(acc2[2 * j2], vv, w.x);
            ffma2(acc2[2 * j2 + 1], vv, w.y);
        }
    }
    float o = b2s;
#pragma unroll
    for (int j = 0; j < L / 2; j++) {
        float2 u = unpack2(acc2[j]);
        o = fmaf(lk(u.x), w2s[2 * j], o);
        o = fmaf(lk(u.y), w2s[2 * j + 1], o);
    }
    out[n] = o;
}

// ---------------- launch ------------------------------------------------------
extern "C" void kernel_launch(void* const* d_in, const int* in_sizes, int n_in,
                              void* d_out, int out_size) {
    const float* x    = (const float*)d_in[0];
    const float* ea   = (const float*)d_in[1];
    const int*   snd  = (const int*)d_in[2];
    const int*   rcv  = (const int*)d_in[3];
    const float* neW  = (const float*)d_in[4];
    const float* neb  = (const float*)d_in[5];
    const float* eeW  = (const float*)d_in[6];
    const float* eeb  = (const float*)d_in[7];
    const float* eW   = (const float*)d_in[8];
    const float* eb   = (const float*)d_in[9];
    const float* els  = (const float*)d_in[10];
    const float* elb  = (const float*)d_in[11];
    const float* nW   = (const float*)d_in[12];
    const float* nb   = (const float*)d_in[13];
    const float* nls  = (const float*)d_in[14];
    const float* nlb  = (const float*)d_in[15];
    const float* dW1  = (const float*)d_in[16];
    const float* db1  = (const float*)d_in[17];
    const float* dW2  = (const float*)d_in[18];
    const float* db2  = (const float*)d_in[19];
    float* out = (float*)d_out;

    const int TB = 256;
    const int NB_N  = (NN + TB - 1) / TB;
    const int NB_E  = (NE + TB - 1) / TB;
    const int NB_AG = (NN * L + TB - 1) / TB;

    zero_cnt_agg_k<<<NB_AG, TB>>>();   // zeroes cnt and agg (agg once; steps self-zero)
    node_enc_k<<<NB_N, TB>>>(x, neW, neb);
    edge_enc_k<<<NB_E, TB>>>(ea, eeW, eeb, rcv);
    inv_k<<<NB_N, TB>>>();

    for (int s = 0; s < NSTEP; s++) {
        edge_step_k<<<NB_E, TB>>>(eW + (size_t)s * 3 * L * L, eb + (size_t)s * L,
                                  els + (size_t)s * L, elb + (size_t)s * L, snd, rcv);
        node_step_k<<<NB_N, TB>>>(nW + (size_t)s * 2 * L * L, nb + (size_t)s * L,
                                  nls + (size_t)s * L, nlb + (size_t)s * L);
    }
    dec_k<<<NB_N, TB>>>(dW1, db1, dW2, db2, out);
}

// round 15
// speedup vs baseline: 1.2245x; 1.2245x over previous
#include <cuda_runtime.h>

#define NN 50000
#define NE 800000
#define L  32
#define NSTEP 10

// ---------------- scratch (device globals; no allocations allowed) ----------
__device__ float g_h[NN * L];       // node latents
__device__ float g_e[NE * L];       // edge latents
__device__ float g_p[NN * 2 * L];   // per-step node projections [h@W_s | h@W_d]
__device__ float g_agg[NN * L];     // per-step scatter accumulator
__device__ float g_inv[NN];         // 1/max(indeg,1)
__device__ float g_cnt[NN];         // receiver in-degree

__device__ __forceinline__ float lk(float v) { return v >= 0.f ? v : 0.01f * v; }

// --- packed f32x2 helpers (FFMA2 path; sm_100+) ------------------------------
__device__ __forceinline__ unsigned long long pack2(float x, float y) {
    unsigned long long r;
    asm("mov.b64 %0, {%1, %2};" : "=l"(r) : "f"(x), "f"(y));
    return r;
}
__device__ __forceinline__ void ffma2(unsigned long long& d, unsigned long long a,
                                      unsigned long long b) {
    asm("fma.rn.f32x2 %0, %1, %2, %0;" : "+l"(d) : "l"(a), "l"(b));
}
__device__ __forceinline__ float2 unpack2(unsigned long long v) {
    float2 r;
    asm("mov.b64 {%0, %1}, %2;" : "=f"(r.x), "=f"(r.y) : "l"(v));
    return r;
}
__device__ __forceinline__ void red_v4(float* p, float4 o) {
    asm volatile("red.global.add.v4.f32 [%0], {%1, %2, %3, %4};"
                 :: "l"(p), "f"(o.x), "f"(o.y), "f"(o.z), "f"(o.w) : "memory");
}

// ---------------- tiny utility kernels --------------------------------------
__global__ void zero_cnt_agg_k() {
    int i = blockIdx.x * blockDim.x + threadIdx.x;
    if (i < NN) g_cnt[i] = 0.f;
    if (i < NN * L) g_agg[i] = 0.f;
}

__global__ void inv_k() {
    int i = blockIdx.x * blockDim.x + threadIdx.x;
    if (i < NN) g_inv[i] = 1.f / fmaxf(g_cnt[i], 1.f);
}

// ---------------- encoders --------------------------------------------------
__global__ __launch_bounds__(256) void node_enc_k(
    const float* __restrict__ x, const float* __restrict__ W,
    const float* __restrict__ b) {
    __shared__ float Ws[6 * L];
    __shared__ float bs[L];
    int t = threadIdx.x;
    if (t < 6 * L) Ws[t] = W[t];
    if (t < L) bs[t] = b[t];
    __syncthreads();
    int n = blockIdx.x * blockDim.x + t;
    if (n >= NN) return;
    float in[6];
#pragma unroll
    for (int k = 0; k < 6; k++) in[k] = x[n * 6 + k];
#pragma unroll
    for (int j = 0; j < L; j += 4) {
        float4 a = make_float4(bs[j], bs[j + 1], bs[j + 2], bs[j + 3]);
#pragma unroll
        for (int k = 0; k < 6; k++) {
            float4 w = *(const float4*)&Ws[k * L + j];
            a.x = fmaf(in[k], w.x, a.x);
            a.y = fmaf(in[k], w.y, a.y);
            a.z = fmaf(in[k], w.z, a.z);
            a.w = fmaf(in[k], w.w, a.w);
        }
        float4 o = make_float4(lk(a.x), lk(a.y), lk(a.z), lk(a.w));
        *(float4*)&g_h[(size_t)n * L + j] = o;
    }
}

__global__ __launch_bounds__(256) void edge_enc_k(
    const float* __restrict__ ea, const float* __restrict__ W,
    const float* __restrict__ b, const int* __restrict__ rcv) {
    __shared__ float Ws[3 * L];
    __shared__ float bs[L];
    int t = threadIdx.x;
    if (t < 3 * L) Ws[t] = W[t];
    if (t < L) bs[t] = b[t];
    __syncthreads();
    int eid = blockIdx.x * blockDim.x + t;
    if (eid >= NE) return;
    float in[3];
#pragma unroll
    for (int k = 0; k < 3; k++) in[k] = ea[(size_t)eid * 3 + k];
#pragma unroll
    for (int j = 0; j < L; j += 4) {
        float4 a = make_float4(bs[j], bs[j + 1], bs[j + 2], bs[j + 3]);
#pragma unroll
        for (int k = 0; k < 3; k++) {
            float4 w = *(const float4*)&Ws[k * L + j];
            a.x = fmaf(in[k], w.x, a.x);
            a.y = fmaf(in[k], w.y, a.y);
            a.z = fmaf(in[k], w.z, a.z);
            a.w = fmaf(in[k], w.w, a.w);
        }
        float4 o = make_float4(lk(a.x), lk(a.y), lk(a.z), lk(a.w));
        *(float4*)&g_e[(size_t)eid * L + j] = o;
    }
    atomicAdd(&g_cnt[rcv[eid]], 1.f);  // in-degree (reused all steps)
}

// ---------------- per-step node projection ------------------------------------
// p[n] = [ h[n] @ W[L:2L, :] | h[n] @ W[2L:3L, :] ]   (exact split of edge MLP)
__global__ __launch_bounds__(256) void proj_k(const float* __restrict__ W) {
    __shared__ __align__(16) float Ws[2 * L * L];   // 8 KB: rows L..3L-1 of W
    int n = blockIdx.x * blockDim.x + threadIdx.x;
    bool active = n < NN;
    float hin[L];
    if (active) {
        const float* hrow = &g_h[(size_t)n * L];
#pragma unroll
        for (int j = 0; j < L; j += 4) *(float4*)&hin[j] = *(const float4*)&hrow[j];
    }
    for (int i = threadIdx.x; i < 2 * L * L; i += 256) Ws[i] = W[L * L + i];
    __syncthreads();
    if (!active) return;

    unsigned long long acc2[L];   // 64 outputs: [0..15]=src proj, [16..31]=dst proj
#pragma unroll
    for (int j = 0; j < L; j++) acc2[j] = 0ull;

#pragma unroll
    for (int k = 0; k < L; k++) {
        unsigned long long vv = pack2(hin[k], hin[k]);
        const ulonglong2* wsrc = (const ulonglong2*)&Ws[k * L];         // W_s row k
        const ulonglong2* wdst = (const ulonglong2*)&Ws[(L + k) * L];   // W_d row k
#pragma unroll
        for (int j2 = 0; j2 < L / 4; j2++) {
            ulonglong2 a = wsrc[j2];
            ffma2(acc2[2 * j2], vv, a.x);
            ffma2(acc2[2 * j2 + 1], vv, a.y);
            ulonglong2 d = wdst[j2];
            ffma2(acc2[L / 2 + 2 * j2], vv, d.x);
            ffma2(acc2[L / 2 + 2 * j2 + 1], vv, d.y);
        }
    }

    float* prow = &g_p[(size_t)n * 2 * L];
    // store src half then dst half
#pragma unroll
    for (int j = 0; j < L / 2; j++) {
        float2 u = unpack2(acc2[j]);
        prow[2 * j] = u.x;
        prow[2 * j + 1] = u.y;
    }
#pragma unroll
    for (int j = 0; j < L / 2; j++) {
        float2 u = unpack2(acc2[L / 2 + j]);
        prow[L + 2 * j] = u.x;
        prow[L + 2 * j + 1] = u.y;
    }
}

// ---------------- per-step edge update (the hot kernel) ----------------------
// m = LN(leaky(b + p_s[snd] + p_d[rcv] + e@W_e)); e += m; agg[rcv] += e
__global__ __launch_bounds__(256) void edge_step_k(
    const float* __restrict__ W, const float* __restrict__ b,
    const float* __restrict__ lns, const float* __restrict__ lnb,
    const int* __restrict__ snd, const int* __restrict__ rcv) {
    __shared__ __align__(16) float Ws[L * L];   // 4 KB: rows 0..L-1 (e part)
    __shared__ float bs[L], ss[L], os[L];

    // prefetch indices + own e row before weight staging
    int eid = blockIdx.x * blockDim.x + threadIdx.x;
    bool active = eid < NE;
    int s = 0, r = 0;
    float ein[L];
    float* erow = &g_e[(size_t)(active ? eid : 0) * L];
    if (active) {
        s = snd[eid];
        r = rcv[eid];
#pragma unroll
        for (int j = 0; j < L; j += 4) *(float4*)&ein[j] = *(const float4*)&erow[j];
    }

    for (int i = threadIdx.x; i < L * L; i += 256) Ws[i] = W[i];
    if (threadIdx.x < L) {
        bs[threadIdx.x] = b[threadIdx.x];
        ss[threadIdx.x] = lns[threadIdx.x];
        os[threadIdx.x] = lnb[threadIdx.x];
    }
    __syncthreads();
    if (!active) return;

    // e @ W_e accumulated packed, bias folded in
    unsigned long long acc2[L / 2];
#pragma unroll
    for (int j = 0; j < L / 2; j++) acc2[j] = pack2(bs[2 * j], bs[2 * j + 1]);
#pragma unroll
    for (int k = 0; k < L; k++) {
        unsigned long long vv = pack2(ein[k], ein[k]);
        const ulonglong2* wrow = (const ulonglong2*)&Ws[k * L];
#pragma unroll
        for (int j2 = 0; j2 < L / 4; j2++) {
            ulonglong2 w = wrow[j2];
            ffma2(acc2[2 * j2], vv, w.x);
            ffma2(acc2[2 * j2 + 1], vv, w.y);
        }
    }

    // add gathered node projections (128 B each, L2-resident table)
    float acc[L];
#pragma unroll
    for (int j = 0; j < L / 2; j++) {
        float2 u = unpack2(acc2[j]);
        acc[2 * j] = u.x;
        acc[2 * j + 1] = u.y;
    }
    const float* ps = &g_p[(size_t)s * 2 * L];       // src projection half
    const float* pd = &g_p[(size_t)r * 2 * L + L];   // dst projection half
#pragma unroll
    for (int j = 0; j < L; j += 4) {
        float4 a = *(const float4*)&ps[j];
        float4 d = *(const float4*)&pd[j];
        acc[j]     += a.x + d.x;
        acc[j + 1] += a.y + d.y;
        acc[j + 2] += a.z + d.z;
        acc[j + 3] += a.w + d.w;
    }

    // LeakyReLU + thread-local LayerNorm
    float mu = 0.f;
#pragma unroll
    for (int j = 0; j < L; j++) { acc[j] = lk(acc[j]); mu += acc[j]; }
    mu *= (1.f / L);
    float var = 0.f;
#pragma unroll
    for (int j = 0; j < L; j++) { float d = acc[j] - mu; var = fmaf(d, d, var); }
    float rs = rsqrtf(var * (1.f / L) + 1e-5f);

    float* arow = &g_agg[(size_t)r * L];
#pragma unroll
    for (int j = 0; j < L; j += 4) {
        float4 o;
        o.x = ein[j]     + fmaf((acc[j]     - mu) * rs, ss[j],     os[j]);
        o.y = ein[j + 1] + fmaf((acc[j + 1] - mu) * rs, ss[j + 1], os[j + 1]);
        o.z = ein[j + 2] + fmaf((acc[j + 2] - mu) * rs, ss[j + 2], os[j + 2]);
        o.w = ein[j + 3] + fmaf((acc[j + 3] - mu) * rs, ss[j + 3], os[j + 3]);
        *(float4*)&erow[j] = o;
        red_v4(&arow[j], o);
    }
}

// ---------------- per-step node update ---------------------------------------
// u = LN(leaky(concat(h, agg*inv) @ W[64,32] + b)); h += u; then zero agg row
__global__ __launch_bounds__(256) void node_step_k(
    const float* __restrict__ W, const float* __restrict__ b,
    const float* __restrict__ lns, const float* __restrict__ lnb) {
    __shared__ __align__(16) float Ws[2 * L * L];  // 8 KB
    __shared__ float bs[L], ss[L], os[L];

    int n = blockIdx.x * blockDim.x + threadIdx.x;
    bool active = n < NN;
    float inv = 0.f;
    float in[L], hin[L];
    float* arow = &g_agg[(size_t)(active ? n : 0) * L];
    float* hrow = &g_h[(size_t)(active ? n : 0) * L];
    if (active) {
        inv = g_inv[n];
#pragma unroll
        for (int j = 0; j < L; j += 4) {
            *(float4*)&in[j] = *(const float4*)&arow[j];
            *(float4*)&hin[j] = *(const float4*)&hrow[j];
        }
    }

    for (int i = threadIdx.x; i < 2 * L * L; i += 256) Ws[i] = W[i];
    if (threadIdx.x < L) {
        bs[threadIdx.x] = b[threadIdx.x];
        ss[threadIdx.x] = lns[threadIdx.x];
        os[threadIdx.x] = lnb[threadIdx.x];
    }
    __syncthreads();
    if (!active) return;

#pragma unroll
    for (int j = 0; j < L; j += 4)
        *(float4*)&arow[j] = make_float4(0.f, 0.f, 0.f, 0.f);

    unsigned long long acc2[L / 2];
#pragma unroll
    for (int j = 0; j < L / 2; j++) acc2[j] = pack2(bs[2 * j], bs[2 * j + 1]);

#pragma unroll
    for (int k = 0; k < L; k++) {
        float v = in[k] * inv;
        unsigned long long vv = pack2(v, v);
        const ulonglong2* wrow = (const ulonglong2*)&Ws[(L + k) * L];
#pragma unroll
        for (int j2 = 0; j2 < L / 4; j2++) {
            ulonglong2 w = wrow[j2];
            ffma2(acc2[2 * j2], vv, w.x);
            ffma2(acc2[2 * j2 + 1], vv, w.y);
        }
    }
#pragma unroll
    for (int k = 0; k < L; k++) {
        unsigned long long vv = pack2(hin[k], hin[k]);
        const ulonglong2* wrow = (const ulonglong2*)&Ws[k * L];
#pragma unroll
        for (int j2 = 0; j2 < L / 4; j2++) {
            ulonglong2 w = wrow[j2];
            ffma2(acc2[2 * j2], vv, w.x);
            ffma2(acc2[2 * j2 + 1], vv, w.y);
        }
    }

    float acc[L];
#pragma unroll
    for (int j = 0; j < L / 2; j++) {
        float2 u = unpack2(acc2[j]);
        acc[2 * j] = lk(u.x);
        acc[2 * j + 1] = lk(u.y);
    }
    float mu = 0.f;
#pragma unroll
    for (int j = 0; j < L; j++) mu += acc[j];
    mu *= (1.f / L);
    float var = 0.f;
#pragma unroll
    for (int j = 0; j < L; j++) { float d = acc[j] - mu; var = fmaf(d, d, var); }
    float rs = rsqrtf(var * (1.f / L) + 1e-5f);

#pragma unroll
    for (int j = 0; j < L; j += 4) {
        float4 o;
        o.x = hin[j]     + fmaf((acc[j]     - mu) * rs, ss[j],     os[j]);
        o.y = hin[j + 1] + fmaf((acc[j + 1] - mu) * rs, ss[j + 1], os[j + 1]);
        o.z = hin[j + 2] + fmaf((acc[j + 2] - mu) * rs, ss[j + 2], os[j + 2]);
        o.w = hin[j + 3] + fmaf((acc[j + 3] - mu) * rs, ss[j + 3], os[j + 3]);
        *(float4*)&hrow[j] = o;
    }
}

// ---------------- decoder -----------------------------------------------------
__global__ __launch_bounds__(256) void dec_k(
    const float* __restrict__ W1, const float* __restrict__ b1,
    const float* __restrict__ W2, const float* __restrict__ b2,
    float* __restrict__ out) {
    __shared__ __align__(16) float Ws[L * L];
    __shared__ float b1s[L], w2s[L];
    __shared__ float b2s;
    int t = threadIdx.x;

    int n = blockIdx.x * blockDim.x + t;
    bool active = n < NN;
    float in[L];
    if (active) {
        const float* hrow = &g_h[(size_t)n * L];
#pragma unroll
        for (int j = 0; j < L; j += 4) *(float4*)&in[j] = *(const float4*)&hrow[j];
    }

    for (int i = t; i < L * L; i += 256) Ws[i] = W1[i];
    if (t < L) { b1s[t] = b1[t]; w2s[t] = W2[t]; }
    if (t == 0) b2s = b2[0];
    __syncthreads();
    if (!active) return;

    unsigned long long acc2[L / 2];
#pragma unroll
    for (int j = 0; j < L / 2; j++) acc2[j] = pack2(b1s[2 * j], b1s[2 * j + 1]);
#pragma unroll
    for (int k = 0; k < L; k++) {
        unsigned long long vv = pack2(in[k], in[k]);
        const ulonglong2* wrow = (const ulonglong2*)&Ws[k * L];
#pragma unroll
        for (int j2 = 0; j2 < L / 4; j2++) {
            ulonglong2 w = wrow[j2];
            ffma2(acc2[2 * j2], vv, w.x);
            ffma2(acc2[2 * j2 + 1], vv, w.y);
        }
    }
    float o = b2s;
#pragma unroll
    for (int j = 0; j < L / 2; j++) {
        float2 u = unpack2(acc2[j]);
        o = fmaf(lk(u.x), w2s[2 * j], o);
        o = fmaf(lk(u.y), w2s[2 * j + 1], o);
    }
    out[n] = o;
}

// ---------------- launch ------------------------------------------------------
extern "C" void kernel_launch(void* const* d_in, const int* in_sizes, int n_in,
                              void* d_out, int out_size) {
    const float* x    = (const float*)d_in[0];
    const float* ea   = (const float*)d_in[1];
    const int*   snd  = (const int*)d_in[2];
    const int*   rcv  = (const int*)d_in[3];
    const float* neW  = (const float*)d_in[4];
    const float* neb  = (const float*)d_in[5];
    const float* eeW  = (const float*)d_in[6];
    const float* eeb  = (const float*)d_in[7];
    const float* eW   = (const float*)d_in[8];
    const float* eb   = (const float*)d_in[9];
    const float* els  = (const float*)d_in[10];
    const float* elb  = (const float*)d_in[11];
    const float* nW   = (const float*)d_in[12];
    const float* nb   = (const float*)d_in[13];
    const float* nls  = (const float*)d_in[14];
    const float* nlb  = (const float*)d_in[15];
    const float* dW1  = (const float*)d_in[16];
    const float* db1  = (const float*)d_in[17];
    const float* dW2  = (const float*)d_in[18];
    const float* db2  = (const float*)d_in[19];
    float* out = (float*)d_out;

    const int TB = 256;
    const int NB_N  = (NN + TB - 1) / TB;
    const int NB_E  = (NE + TB - 1) / TB;
    const int NB_AG = (NN * L + TB - 1) / TB;

    zero_cnt_agg_k<<<NB_AG, TB>>>();
    node_enc_k<<<NB_N, TB>>>(x, neW, neb);
    edge_enc_k<<<NB_E, TB>>>(ea, eeW, eeb, rcv);
    inv_k<<<NB_N, TB>>>();

    for (int s = 0; s < NSTEP; s++) {
        const float* Wstep = eW + (size_t)s * 3 * L * L;
        proj_k<<<NB_N, TB>>>(Wstep);
        edge_step_k<<<NB_E, TB>>>(Wstep, eb + (size_t)s * L,
                                  els + (size_t)s * L, elb + (size_t)s * L, snd, rcv);
        node_step_k<<<NB_N, TB>>>(nW + (size_t)s * 2 * L * L, nb + (size_t)s * L,
                                  nls + (size_t)s * L, nlb + (size_t)s * L);
    }
    dec_k<<<NB_N, TB>>>(dW1, db1, dW2, db2, out);
}

// round 17
// speedup vs baseline: 1.2759x; 1.0420x over previous
#include <cuda_runtime.h>

#define NN 50000
#define NE 800000
#define L  32
#define NSTEP 10
#define NBLK 196   // ceil(NN/256)

// ---------------- scratch (device globals; no allocations allowed) ----------
__device__ float g_h[NN * L];       // node latents
__device__ float g_e[NE * L];       // edge latents
__device__ float g_p[NN * 2 * L];   // per-step node projections [h@W_s | h@W_d]
__device__ float g_agg[NN * L];     // per-step aggregation result
__device__ float g_cnt[NN];         // receiver in-degree histogram
__device__ int   g_off[NN + 1];     // CSR offsets
__device__ int   g_cur[NN];         // fill cursors
__device__ int   g_bsum[256];       // block sums for scan
__device__ int   g_eidx[NE];        // CSR edge ids (grouped by receiver)

__device__ __forceinline__ float lk(float v) { return v >= 0.f ? v : 0.01f * v; }

// --- packed f32x2 helpers (FFMA2 path; sm_100+) ------------------------------
__device__ __forceinline__ unsigned long long pack2(float x, float y) {
    unsigned long long r;
    asm("mov.b64 %0, {%1, %2};" : "=l"(r) : "f"(x), "f"(y));
    return r;
}
__device__ __forceinline__ void ffma2(unsigned long long& d, unsigned long long a,
                                      unsigned long long b) {
    asm("fma.rn.f32x2 %0, %1, %2, %0;" : "+l"(d) : "l"(a), "l"(b));
}
__device__ __forceinline__ float2 unpack2(unsigned long long v) {
    float2 r;
    asm("mov.b64 {%0, %1}, %2;" : "=f"(r.x), "=f"(r.y) : "l"(v));
    return r;
}

// ---------------- CSR build ---------------------------------------------------
__global__ void zero_cnt_k() {
    int i = blockIdx.x * blockDim.x + threadIdx.x;
    if (i < NN) g_cnt[i] = 0.f;
}

__global__ void scan1_k() {   // per-block exclusive scan of cnt
    __shared__ int sh[256];
    int i = blockIdx.x * 256 + threadIdx.x;
    int v = (i < NN) ? (int)g_cnt[i] : 0;
    sh[threadIdx.x] = v;
    __syncthreads();
    for (int d = 1; d < 256; d <<= 1) {
        int t = (threadIdx.x >= d) ? sh[threadIdx.x - d] : 0;
        __syncthreads();
        sh[threadIdx.x] += t;
        __syncthreads();
    }
    if (i < NN) g_off[i] = sh[threadIdx.x] - v;     // exclusive
    if (threadIdx.x == 255) g_bsum[blockIdx.x] = sh[255];
}

__global__ void scan2_k() {   // exclusive scan of the 196 block sums (1 block)
    __shared__ int sh[256];
    int t = threadIdx.x;
    int v = (t < NBLK) ? g_bsum[t] : 0;
    sh[t] = v;
    __syncthreads();
    for (int d = 1; d < 256; d <<= 1) {
        int x = (t >= d) ? sh[t - d] : 0;
        __syncthreads();
        sh[t] += x;
        __syncthreads();
    }
    if (t < NBLK) g_bsum[t] = sh[t] - v;
}

__global__ void scan3_k() {   // add block offsets; init cursors; close sentinel
    int i = blockIdx.x * blockDim.x + threadIdx.x;
    if (i < NN) {
        int o = g_off[i] + g_bsum[i >> 8];
        g_off[i] = o;
        g_cur[i] = o;
    }
    if (i == 0) g_off[NN] = NE;
}

__global__ void fill_k(const int* __restrict__ rcv) {
    int e = blockIdx.x * blockDim.x + threadIdx.x;
    if (e >= NE) return;
    int pos = atomicAdd(&g_cur[rcv[e]], 1);
    g_eidx[pos] = e;
}

// ---------------- encoders --------------------------------------------------
__global__ __launch_bounds__(256) void node_enc_k(
    const float* __restrict__ x, const float* __restrict__ W,
    const float* __restrict__ b) {
    __shared__ float Ws[6 * L];
    __shared__ float bs[L];
    int t = threadIdx.x;
    if (t < 6 * L) Ws[t] = W[t];
    if (t < L) bs[t] = b[t];
    __syncthreads();
    int n = blockIdx.x * blockDim.x + t;
    if (n >= NN) return;
    float in[6];
#pragma unroll
    for (int k = 0; k < 6; k++) in[k] = x[n * 6 + k];
#pragma unroll
    for (int j = 0; j < L; j += 4) {
        float4 a = make_float4(bs[j], bs[j + 1], bs[j + 2], bs[j + 3]);
#pragma unroll
        for (int k = 0; k < 6; k++) {
            float4 w = *(const float4*)&Ws[k * L + j];
            a.x = fmaf(in[k], w.x, a.x);
            a.y = fmaf(in[k], w.y, a.y);
            a.z = fmaf(in[k], w.z, a.z);
            a.w = fmaf(in[k], w.w, a.w);
        }
        float4 o = make_float4(lk(a.x), lk(a.y), lk(a.z), lk(a.w));
        *(float4*)&g_h[(size_t)n * L + j] = o;
    }
}

__global__ __launch_bounds__(256) void edge_enc_k(
    const float* __restrict__ ea, const float* __restrict__ W,
    const float* __restrict__ b, const int* __restrict__ rcv) {
    __shared__ float Ws[3 * L];
    __shared__ float bs[L];
    int t = threadIdx.x;
    if (t < 3 * L) Ws[t] = W[t];
    if (t < L) bs[t] = b[t];
    __syncthreads();
    int eid = blockIdx.x * blockDim.x + t;
    if (eid >= NE) return;
    float in[3];
#pragma unroll
    for (int k = 0; k < 3; k++) in[k] = ea[(size_t)eid * 3 + k];
#pragma unroll
    for (int j = 0; j < L; j += 4) {
        float4 a = make_float4(bs[j], bs[j + 1], bs[j + 2], bs[j + 3]);
#pragma unroll
        for (int k = 0; k < 3; k++) {
            float4 w = *(const float4*)&Ws[k * L + j];
            a.x = fmaf(in[k], w.x, a.x);
            a.y = fmaf(in[k], w.y, a.y);
            a.z = fmaf(in[k], w.z, a.z);
            a.w = fmaf(in[k], w.w, a.w);
        }
        float4 o = make_float4(lk(a.x), lk(a.y), lk(a.z), lk(a.w));
        *(float4*)&g_e[(size_t)eid * L + j] = o;
    }
    atomicAdd(&g_cnt[rcv[eid]], 1.f);  // in-degree histogram (CSR build)
}

// ---------------- per-step node projection ------------------------------------
// p[n] = [ h[n] @ W[L:2L, :] | h[n] @ W[2L:3L, :] ]   (exact split of edge MLP)
__global__ __launch_bounds__(256) void proj_k(const float* __restrict__ W) {
    __shared__ __align__(16) float Ws[2 * L * L];   // 8 KB: rows L..3L-1 of W
    int n = blockIdx.x * blockDim.x + threadIdx.x;
    bool active = n < NN;
    float hin[L];
    if (active) {
        const float* hrow = &g_h[(size_t)n * L];
#pragma unroll
        for (int j = 0; j < L; j += 4) *(float4*)&hin[j] = *(const float4*)&hrow[j];
    }
    for (int i = threadIdx.x; i < 2 * L * L; i += 256) Ws[i] = W[L * L + i];
    __syncthreads();
    if (!active) return;

    unsigned long long acc2[L];
#pragma unroll
    for (int j = 0; j < L; j++) acc2[j] = 0ull;

#pragma unroll
    for (int k = 0; k < L; k++) {
        unsigned long long vv = pack2(hin[k], hin[k]);
        const ulonglong2* wsrc = (const ulonglong2*)&Ws[k * L];
        const ulonglong2* wdst = (const ulonglong2*)&Ws[(L + k) * L];
#pragma unroll
        for (int j2 = 0; j2 < L / 4; j2++) {
            ulonglong2 a = wsrc[j2];
            ffma2(acc2[2 * j2], vv, a.x);
            ffma2(acc2[2 * j2 + 1], vv, a.y);
            ulonglong2 d = wdst[j2];
            ffma2(acc2[L / 2 + 2 * j2], vv, d.x);
            ffma2(acc2[L / 2 + 2 * j2 + 1], vv, d.y);
        }
    }

    float* prow = &g_p[(size_t)n * 2 * L];
#pragma unroll
    for (int j = 0; j < L / 2; j++) {
        float2 u = unpack2(acc2[j]);
        prow[2 * j] = u.x;
        prow[2 * j + 1] = u.y;
    }
#pragma unroll
    for (int j = 0; j < L / 2; j++) {
        float2 u = unpack2(acc2[L / 2 + j]);
        prow[L + 2 * j] = u.x;
        prow[L + 2 * j + 1] = u.y;
    }
}

// ---------------- per-step edge update (no atomics anymore) -------------------
// m = LN(leaky(b + p_s[snd] + p_d[rcv] + e@W_e)); e += m
__global__ __launch_bounds__(256) void edge_step_k(
    const float* __restrict__ W, const float* __restrict__ b,
    const float* __restrict__ lns, const float* __restrict__ lnb,
    const int* __restrict__ snd, const int* __restrict__ rcv) {
    __shared__ __align__(16) float Ws[L * L];   // 4 KB: rows 0..L-1 (e part)
    __shared__ float bs[L], ss[L], os[L];

    int eid = blockIdx.x * blockDim.x + threadIdx.x;
    bool active = eid < NE;
    int s = 0, r = 0;
    float ein[L];
    float* erow = &g_e[(size_t)(active ? eid : 0) * L];
    if (active) {
        s = snd[eid];
        r = rcv[eid];
#pragma unroll
        for (int j = 0; j < L; j += 4) *(float4*)&ein[j] = *(const float4*)&erow[j];
    }

    for (int i = threadIdx.x; i < L * L; i += 256) Ws[i] = W[i];
    if (threadIdx.x < L) {
        bs[threadIdx.x] = b[threadIdx.x];
        ss[threadIdx.x] = lns[threadIdx.x];
        os[threadIdx.x] = lnb[threadIdx.x];
    }
    __syncthreads();
    if (!active) return;

    unsigned long long acc2[L / 2];
#pragma unroll
    for (int j = 0; j < L / 2; j++) acc2[j] = pack2(bs[2 * j], bs[2 * j + 1]);
#pragma unroll
    for (int k = 0; k < L; k++) {
        unsigned long long vv = pack2(ein[k], ein[k]);
        const ulonglong2* wrow = (const ulonglong2*)&Ws[k * L];
#pragma unroll
        for (int j2 = 0; j2 < L / 4; j2++) {
            ulonglong2 w = wrow[j2];
            ffma2(acc2[2 * j2], vv, w.x);
            ffma2(acc2[2 * j2 + 1], vv, w.y);
        }
    }

    float acc[L];
#pragma unroll
    for (int j = 0; j < L / 2; j++) {
        float2 u = unpack2(acc2[j]);
        acc[2 * j] = u.x;
        acc[2 * j + 1] = u.y;
    }
    const float* ps = &g_p[(size_t)s * 2 * L];
    const float* pd = &g_p[(size_t)r * 2 * L + L];
#pragma unroll
    for (int j = 0; j < L; j += 4) {
        float4 a = *(const float4*)&ps[j];
        float4 d = *(const float4*)&pd[j];
        acc[j]     += a.x + d.x;
        acc[j + 1] += a.y + d.y;
        acc[j + 2] += a.z + d.z;
        acc[j + 3] += a.w + d.w;
    }

    float mu = 0.f;
#pragma unroll
    for (int j = 0; j < L; j++) { acc[j] = lk(acc[j]); mu += acc[j]; }
    mu *= (1.f / L);
    float var = 0.f;
#pragma unroll
    for (int j = 0; j < L; j++) { float d = acc[j] - mu; var = fmaf(d, d, var); }
    float rs = rsqrtf(var * (1.f / L) + 1e-5f);

#pragma unroll
    for (int j = 0; j < L; j += 4) {
        float4 o;
        o.x = ein[j]     + fmaf((acc[j]     - mu) * rs, ss[j],     os[j]);
        o.y = ein[j + 1] + fmaf((acc[j + 1] - mu) * rs, ss[j + 1], os[j + 1]);
        o.z = ein[j + 2] + fmaf((acc[j + 2] - mu) * rs, ss[j + 2], os[j + 2]);
        o.w = ein[j + 3] + fmaf((acc[j + 3] - mu) * rs, ss[j + 3], os[j + 3]);
        *(float4*)&erow[j] = o;
    }
}

// ---------------- per-step aggregation (CSR gather, warp-per-node) -----------
__global__ __launch_bounds__(256) void agg_k() {
    int gw = (blockIdx.x * 256 + threadIdx.x) >> 5;   // node id
    int lane = threadIdx.x & 31;
    if (gw >= NN) return;
    int beg = g_off[gw], end = g_off[gw + 1];
    int rowg = lane >> 3;        // 0..3: which edge in flight
    int colg = lane & 7;         // 0..7: which float4 of the row
    float4 acc = make_float4(0.f, 0.f, 0.f, 0.f);
    for (int it = beg + rowg; it < end; it += 4) {
        int eid = g_eidx[it];
        float4 v = *(const float4*)&g_e[(size_t)eid * L + colg * 4];
        acc.x += v.x; acc.y += v.y; acc.z += v.z; acc.w += v.w;
    }
    // reduce the 4 row-groups (lanes differing in bits 3,4)
#pragma unroll
    for (int d = 8; d <= 16; d <<= 1) {
        acc.x += __shfl_xor_sync(0xffffffffu, acc.x, d);
        acc.y += __shfl_xor_sync(0xffffffffu, acc.y, d);
        acc.z += __shfl_xor_sync(0xffffffffu, acc.z, d);
        acc.w += __shfl_xor_sync(0xffffffffu, acc.w, d);
    }
    if (lane < 8)
        *(float4*)&g_agg[(size_t)gw * L + colg * 4] = acc;
}

// ---------------- per-step node update ---------------------------------------
// u = LN(leaky(concat(h, agg/deg) @ W[64,32] + b)); h += u
__global__ __launch_bounds__(256) void node_step_k(
    const float* __restrict__ W, const float* __restrict__ b,
    const float* __restrict__ lns, const float* __restrict__ lnb) {
    __shared__ __align__(16) float Ws[2 * L * L];  // 8 KB
    __shared__ float bs[L], ss[L], os[L];

    int n = blockIdx.x * blockDim.x + threadIdx.x;
    bool active = n < NN;
    float inv = 0.f;
    float in[L], hin[L];
    float* hrow = &g_h[(size_t)(active ? n : 0) * L];
    if (active) {
        int deg = g_off[n + 1] - g_off[n];
        inv = 1.f / fmaxf((float)deg, 1.f);
        const float* arow = &g_agg[(size_t)n * L];
#pragma unroll
        for (int j = 0; j < L; j += 4) {
            *(float4*)&in[j] = *(const float4*)&arow[j];
            *(float4*)&hin[j] = *(const float4*)&hrow[j];
        }
    }

    for (int i = threadIdx.x; i < 2 * L * L; i += 256) Ws[i] = W[i];
    if (threadIdx.x < L) {
        bs[threadIdx.x] = b[threadIdx.x];
        ss[threadIdx.x] = lns[threadIdx.x];
        os[threadIdx.x] = lnb[threadIdx.x];
    }
    __syncthreads();
    if (!active) return;

    unsigned long long acc2[L / 2];
#pragma unroll
    for (int j = 0; j < L / 2; j++) acc2[j] = pack2(bs[2 * j], bs[2 * j + 1]);

#pragma unroll
    for (int k = 0; k < L; k++) {
        float v = in[k] * inv;
        unsigned long long vv = pack2(v, v);
        const ulonglong2* wrow = (const ulonglong2*)&Ws[(L + k) * L];
#pragma unroll
        for (int j2 = 0; j2 < L / 4; j2++) {
            ulonglong2 w = wrow[j2];
            ffma2(acc2[2 * j2], vv, w.x);
            ffma2(acc2[2 * j2 + 1], vv, w.y);
        }
    }
#pragma unroll
    for (int k = 0; k < L; k++) {
        unsigned long long vv = pack2(hin[k], hin[k]);
        const ulonglong2* wrow = (const ulonglong2*)&Ws[k * L];
#pragma unroll
        for (int j2 = 0; j2 < L / 4; j2++) {
            ulonglong2 w = wrow[j2];
            ffma2(acc2[2 * j2], vv, w.x);
            ffma2(acc2[2 * j2 + 1], vv, w.y);
        }
    }

    float acc[L];
#pragma unroll
    for (int j = 0; j < L / 2; j++) {
        float2 u = unpack2(acc2[j]);
        acc[2 * j] = lk(u.x);
        acc[2 * j + 1] = lk(u.y);
    }
    float mu = 0.f;
#pragma unroll
    for (int j = 0; j < L; j++) mu += acc[j];
    mu *= (1.f / L);
    float var = 0.f;
#pragma unroll
    for (int j = 0; j < L; j++) { float d = acc[j] - mu; var = fmaf(d, d, var); }
    float rs = rsqrtf(var * (1.f / L) + 1e-5f);

#pragma unroll
    for (int j = 0; j < L; j += 4) {
        float4 o;
        o.x = hin[j]     + fmaf((acc[j]     - mu) * rs, ss[j],     os[j]);
        o.y = hin[j + 1] + fmaf((acc[j + 1] - mu) * rs, ss[j + 1], os[j + 1]);
        o.z = hin[j + 2] + fmaf((acc[j + 2] - mu) * rs, ss[j + 2], os[j + 2]);
        o.w = hin[j + 3] + fmaf((acc[j + 3] - mu) * rs, ss[j + 3], os[j + 3]);
        *(float4*)&hrow[j] = o;
    }
}

// ---------------- decoder -----------------------------------------------------
__global__ __launch_bounds__(256) void dec_k(
    const float* __restrict__ W1, const float* __restrict__ b1,
    const float* __restrict__ W2, const float* __restrict__ b2,
    float* __restrict__ out) {
    __shared__ __align__(16) float Ws[L * L];
    __shared__ float b1s[L], w2s[L];
    __shared__ float b2s;
    int t = threadIdx.x;

    int n = blockIdx.x * blockDim.x + t;
    bool active = n < NN;
    float in[L];
    if (active) {
        const float* hrow = &g_h[(size_t)n * L];
#pragma unroll
        for (int j = 0; j < L; j += 4) *(float4*)&in[j] = *(const float4*)&hrow[j];
    }

    for (int i = t; i < L * L; i += 256) Ws[i] = W1[i];
    if (t < L) { b1s[t] = b1[t]; w2s[t] = W2[t]; }
    if (t == 0) b2s = b2[0];
    __syncthreads();
    if (!active) return;

    unsigned long long acc2[L / 2];
#pragma unroll
    for (int j = 0; j < L / 2; j++) acc2[j] = pack2(b1s[2 * j], b1s[2 * j + 1]);
#pragma unroll
    for (int k = 0; k < L; k++) {
        unsigned long long vv = pack2(in[k], in[k]);
        const ulonglong2* wrow = (const ulonglong2*)&Ws[k * L];
#pragma unroll
        for (int j2 = 0; j2 < L / 4; j2++) {
            ulonglong2 w = wrow[j2];
            ffma2(acc2[2 * j2], vv, w.x);
            ffma2(acc2[2 * j2 + 1], vv, w.y);
        }
    }
    float o = b2s;
#pragma unroll
    for (int j = 0; j < L / 2; j++) {
        float2 u = unpack2(acc2[j]);
        o = fmaf(lk(u.x), w2s[2 * j], o);
        o = fmaf(lk(u.y), w2s[2 * j + 1], o);
    }
    out[n] = o;
}

// ---------------- launch ------------------------------------------------------
extern "C" void kernel_launch(void* const* d_in, const int* in_sizes, int n_in,
                              void* d_out, int out_size) {
    const float* x    = (const float*)d_in[0];
    const float* ea   = (const float*)d_in[1];
    const int*   snd  = (const int*)d_in[2];
    const int*   rcv  = (const int*)d_in[3];
    const float* neW  = (const float*)d_in[4];
    const float* neb  = (const float*)d_in[5];
    const float* eeW  = (const float*)d_in[6];
    const float* eeb  = (const float*)d_in[7];
    const float* eW   = (const float*)d_in[8];
    const float* eb   = (const float*)d_in[9];
    const float* els  = (const float*)d_in[10];
    const float* elb  = (const float*)d_in[11];
    const float* nW   = (const float*)d_in[12];
    const float* nb   = (const float*)d_in[13];
    const float* nls  = (const float*)d_in[14];
    const float* nlb  = (const float*)d_in[15];
    const float* dW1  = (const float*)d_in[16];
    const float* db1  = (const float*)d_in[17];
    const float* dW2  = (const float*)d_in[18];
    const float* db2  = (const float*)d_in[19];
    float* out = (float*)d_out;

    const int TB = 256;
    const int NB_N  = (NN + TB - 1) / TB;          // 196
    const int NB_E  = (NE + TB - 1) / TB;
    const int NB_W  = (NN * 32 + TB - 1) / TB;     // warp-per-node grid

    zero_cnt_k<<<NB_N, TB>>>();
    node_enc_k<<<NB_N, TB>>>(x, neW, neb);
    edge_enc_k<<<NB_E, TB>>>(ea, eeW, eeb, rcv);
    // CSR build (reused by all steps)
    scan1_k<<<NB_N, TB>>>();
    scan2_k<<<1, TB>>>();
    scan3_k<<<NB_N, TB>>>();
    fill_k<<<NB_E, TB>>>(rcv);

    for (int s = 0; s < NSTEP; s++) {
        const float* Wstep = eW + (size_t)s * 3 * L * L;
        proj_k<<<NB_N, TB>>>(Wstep);
        edge_step_k<<<NB_E, TB>>>(Wstep, eb + (size_t)s * L,
                                  els + (size_t)s * L, elb + (size_t)s * L, snd, rcv);
        agg_k<<<NB_W, TB>>>();
        node_step_k<<<NB_N, TB>>>(nW + (size_t)s * 2 * L * L, nb + (size_t)s * L,
                                  nls + (size_t)s * L, nlb + (size_t)s * L);
    }
    dec_k<<<NB_N, TB>>>(dW1, db1, dW2, db2, out);
}